// round 3
// baseline (speedup 1.0000x reference)
#include <cuda_runtime.h>
#include <math.h>
#include <stdint.h>

// Problem constants (fixed by reference)
#define NN   8192
#define EMB  125
#define POSD 3
#define FIN  128     // EMB + POSD
#define HID  512
#define SLOTS 256

// ---------------- device scratch (no allocation allowed) ----------------
__device__ int   g_col[NN * SLOTS];
__device__ int   g_deg[NN];
__device__ float g_norm[NN];
__device__ float g_bufA[NN * HID];
__device__ float g_bufB[NN * HID];

// ---------------- 1) build sparse structure + norms ----------------
// One warp per row; float4 loads, ballot-compaction (deterministic order).
__global__ void build_kernel(const float* __restrict__ adj) {
    int warp = threadIdx.x >> 5;
    int lane = threadIdx.x & 31;
    int row  = blockIdx.x * (blockDim.x >> 5) + warp;
    if (row >= NN) return;

    const float4* arow = (const float4*)(adj + (size_t)row * NN);
    int cnt = 0;
    for (int c0 = 0; c0 < NN; c0 += 128) {
        float4 v = arow[(c0 >> 2) + lane];
        float vv[4] = {v.x, v.y, v.z, v.w};
#pragma unroll
        for (int q = 0; q < 4; q++) {
            int c = c0 + lane * 4 + q;
            bool pred = (vv[q] != 0.0f) && (c != row);
            unsigned mask = __ballot_sync(0xFFFFFFFFu, pred);
            int pos = cnt + __popc(mask & ((1u << lane) - 1u));
            if (pred && pos < SLOTS) g_col[row * SLOTS + pos] = c;
            cnt += __popc(mask);
        }
    }
    if (lane == 0) {
        g_deg[row]  = (cnt < SLOTS) ? cnt : SLOTS;
        g_norm[row] = rsqrtf(fmaxf((float)cnt, 1.0f));
    }
}

// ---------------- 2) concat emb||pos -> feat [NN, FIN] ----------------
__global__ void concat_kernel(const float* __restrict__ emb,
                              const float* __restrict__ pos,
                              float* __restrict__ out) {
    int idx = blockIdx.x * blockDim.x + threadIdx.x;
    if (idx >= NN * FIN) return;
    int i = idx / FIN, c = idx % FIN;
    out[idx] = (c < EMB) ? emb[i * EMB + c] : pos[i * POSD + (c - EMB)];
}

// ---------------- 3) SpMM (float4/thread, 4x unrolled gather for MLP) ----------------
__global__ void spmm_kernel(const float* __restrict__ feat,
                            float* __restrict__ agg, int C) {
    int i = blockIdx.x;
    int d = g_deg[i];
    __shared__ int   sc[SLOTS];
    __shared__ float sw[SLOTS];
    for (int k = threadIdx.x; k < d; k += blockDim.x) {
        int j = g_col[i * SLOTS + k];
        sc[k] = j;
        sw[k] = g_norm[j];
    }
    __syncthreads();
    int c4 = threadIdx.x * 4;
    float4 acc = make_float4(0.f, 0.f, 0.f, 0.f);
    int k = 0;
    for (; k + 4 <= d; k += 4) {
        float w0 = sw[k], w1 = sw[k + 1], w2 = sw[k + 2], w3 = sw[k + 3];
        float4 v0 = *(const float4*)&feat[(size_t)sc[k]     * C + c4];
        float4 v1 = *(const float4*)&feat[(size_t)sc[k + 1] * C + c4];
        float4 v2 = *(const float4*)&feat[(size_t)sc[k + 2] * C + c4];
        float4 v3 = *(const float4*)&feat[(size_t)sc[k + 3] * C + c4];
        acc.x = fmaf(w0, v0.x, acc.x); acc.y = fmaf(w0, v0.y, acc.y);
        acc.z = fmaf(w0, v0.z, acc.z); acc.w = fmaf(w0, v0.w, acc.w);
        acc.x = fmaf(w1, v1.x, acc.x); acc.y = fmaf(w1, v1.y, acc.y);
        acc.z = fmaf(w1, v1.z, acc.z); acc.w = fmaf(w1, v1.w, acc.w);
        acc.x = fmaf(w2, v2.x, acc.x); acc.y = fmaf(w2, v2.y, acc.y);
        acc.z = fmaf(w2, v2.z, acc.z); acc.w = fmaf(w2, v2.w, acc.w);
        acc.x = fmaf(w3, v3.x, acc.x); acc.y = fmaf(w3, v3.y, acc.y);
        acc.z = fmaf(w3, v3.z, acc.z); acc.w = fmaf(w3, v3.w, acc.w);
    }
    for (; k < d; k++) {
        float w = sw[k];
        float4 v = *(const float4*)&feat[(size_t)sc[k] * C + c4];
        acc.x = fmaf(w, v.x, acc.x); acc.y = fmaf(w, v.y, acc.y);
        acc.z = fmaf(w, v.z, acc.z); acc.w = fmaf(w, v.w, acc.w);
    }
    float ni = g_norm[i];
    acc.x *= ni; acc.y *= ni; acc.z *= ni; acc.w *= ni;
    *(float4*)&agg[(size_t)i * C + c4] = acc;
}

// ---------------- 4) TF32 tensor GEMM + bias + softplus (fragment-packed smem) ----------------
__device__ __forceinline__ uint32_t f2tf32(float f) {
    uint32_t r;
    asm("cvt.rna.tf32.f32 %0, %1;" : "=r"(r) : "f"(f));
    return r;
}

__device__ __forceinline__ void mma_tf32(float* d, const uint32_t* a, const uint32_t* b) {
    asm volatile(
        "mma.sync.aligned.m16n8k8.row.col.f32.tf32.tf32.f32 "
        "{%0,%1,%2,%3}, {%4,%5,%6,%7}, {%8,%9}, {%0,%1,%2,%3};\n"
        : "+f"(d[0]), "+f"(d[1]), "+f"(d[2]), "+f"(d[3])
        : "r"(a[0]), "r"(a[1]), "r"(a[2]), "r"(a[3]), "r"(b[0]), "r"(b[1]));
}

// Block tile 128x128, BK=16, 8 warps (2x4), warp tile 64x32.
// Shared memory holds PRE-PACKED per-lane fragments:
//   PA[buf][kk2][mb][lane][4]  -> one LDS.128 per A fragment
//   PB[buf][kk2][nb][lane][2]  -> one LDS.64  per B fragment
template <int K>
__global__ __launch_bounds__(256) void gemm_tf32_softplus(
    const float* __restrict__ A,
    const float* __restrict__ Bw,
    const float* __restrict__ bias,
    float* __restrict__ Cout)
{
    __shared__ __align__(16) uint32_t PA[2][2][8][32][4];   // 16 KB
    __shared__ __align__(16) uint32_t PB[2][2][16][32][2];  // 16 KB

    int tid  = threadIdx.x;
    int lane = tid & 31;
    int warp = tid >> 5;
    int g    = lane >> 2;     // 0..7
    int tg   = lane & 3;      // 0..3
    int wm   = (warp & 1) * 64;
    int wn   = (warp >> 1) * 32;
    int mb_base = wm >> 4;    // 0 or 4
    int nb_base = wn >> 3;    // 0,4,8,12
    int m0   = blockIdx.y * 128;
    int n0   = blockIdx.x * 128;

    float acc[4][4][4];
#pragma unroll
    for (int i = 0; i < 4; i++)
#pragma unroll
        for (int j = 0; j < 4; j++)
#pragma unroll
            for (int r = 0; r < 4; r++) acc[i][j][r] = 0.0f;

    float4 pa[2], pb[2];

    auto loadg = [&](int k0) {
#pragma unroll
        for (int i = 0; i < 2; i++) {
            int f  = tid * 2 + i;
            int ra = f >> 2,  ca = (f & 3) * 4;
            pa[i] = *(const float4*)&A[(size_t)(m0 + ra) * K + k0 + ca];
            int rb = f >> 5,  cb = (f & 31) * 4;
            pb[i] = *(const float4*)&Bw[(size_t)(k0 + rb) * HID + n0 + cb];
        }
    };
    auto stores = [&](int buf) {
#pragma unroll
        for (int i = 0; i < 2; i++) {
            int f  = tid * 2 + i;
            // A element (row ra, cols ca..ca+3)
            {
                int ra = f >> 2, ca = (f & 3) * 4;
                int mb = ra >> 4, gg = ra & 7, hi = (ra >> 3) & 1;
                int kk2 = ca >> 3, kh = (ca >> 2) & 1;
                uint32_t* p = &PA[buf][kk2][mb][gg * 4][kh * 2 + hi];
                p[0]  = f2tf32(pa[i].x);   // tg = 0..3 -> lane +1 -> +4 words
                p[4]  = f2tf32(pa[i].y);
                p[8]  = f2tf32(pa[i].z);
                p[12] = f2tf32(pa[i].w);
            }
            // B element (k-row rb, cols cb..cb+3)
            {
                int rb = f >> 5, cb = (f & 31) * 4;
                int kk2 = rb >> 3, tgb = rb & 3, kh = (rb >> 2) & 1;
                int g0 = cb & 7, nb = cb >> 3;
                uint32_t* p = &PB[buf][kk2][nb][g0 * 4 + tgb][kh];
                p[0]  = f2tf32(pb[i].x);   // n+1 -> g+1 -> lane +4 -> +8 words
                p[8]  = f2tf32(pb[i].y);
                p[16] = f2tf32(pb[i].z);
                p[24] = f2tf32(pb[i].w);
            }
        }
    };
    auto compute = [&](int buf) {
#pragma unroll
        for (int kk2 = 0; kk2 < 2; kk2++) {
            uint32_t a[4][4], b[4][2];
#pragma unroll
            for (int i = 0; i < 4; i++) {
                uint4 av = *(const uint4*)&PA[buf][kk2][mb_base + i][lane][0];
                a[i][0] = av.x; a[i][1] = av.y; a[i][2] = av.z; a[i][3] = av.w;
            }
#pragma unroll
            for (int j = 0; j < 4; j++) {
                uint2 bv = *(const uint2*)&PB[buf][kk2][nb_base + j][lane][0];
                b[j][0] = bv.x; b[j][1] = bv.y;
            }
#pragma unroll
            for (int i = 0; i < 4; i++)
#pragma unroll
                for (int j = 0; j < 4; j++)
                    mma_tf32(acc[i][j], a[i], b[j]);
        }
    };

    constexpr int NK = K / 16;
    loadg(0);
    stores(0);
    __syncthreads();
#pragma unroll 1
    for (int t = 0; t < NK; t++) {
        if (t + 1 < NK) loadg((t + 1) * 16);
        compute(t & 1);
        if (t + 1 < NK) {
            stores((t + 1) & 1);
            __syncthreads();
        }
    }

    // epilogue: bias + fast stable softplus (MUFU exp/log)
#pragma unroll
    for (int j = 0; j < 4; j++) {
        int col = n0 + wn + j * 8 + tg * 2;
        float bx = bias[col], by = bias[col + 1];
#pragma unroll
        for (int i = 0; i < 4; i++) {
            int row = m0 + wm + i * 16 + g;
            float x0 = acc[i][j][0] + bx;
            float x1 = acc[i][j][1] + by;
            float x2 = acc[i][j][2] + bx;
            float x3 = acc[i][j][3] + by;
            float2 o0, o1;
            o0.x = fmaxf(x0, 0.f) + __logf(1.0f + __expf(-fabsf(x0)));
            o0.y = fmaxf(x1, 0.f) + __logf(1.0f + __expf(-fabsf(x1)));
            o1.x = fmaxf(x2, 0.f) + __logf(1.0f + __expf(-fabsf(x2)));
            o1.y = fmaxf(x3, 0.f) + __logf(1.0f + __expf(-fabsf(x3)));
            *(float2*)&Cout[(size_t)row * HID + col]       = o0;
            *(float2*)&Cout[(size_t)(row + 8) * HID + col] = o1;
        }
    }
}

// ---------------- launch ----------------
extern "C" void kernel_launch(void* const* d_in, const int* in_sizes, int n_in,
                              void* d_out, int out_size) {
    const float* atom_pos = (const float*)d_in[0];
    const float* dist_adj = (const float*)d_in[1];
    const float* atom_emb = (const float*)d_in[2];
    const float* W0 = (const float*)d_in[3];
    const float* b0 = (const float*)d_in[4];
    const float* W1 = (const float*)d_in[5];
    const float* b1 = (const float*)d_in[6];
    const float* W2 = (const float*)d_in[7];
    const float* b2 = (const float*)d_in[8];
    const float* W3 = (const float*)d_in[9];
    const float* b3 = (const float*)d_in[10];
    float* out = (float*)d_out;

    float *bufA, *bufB;
    cudaGetSymbolAddress((void**)&bufA, g_bufA);
    cudaGetSymbolAddress((void**)&bufB, g_bufB);

    build_kernel<<<NN / 8, 256>>>(dist_adj);
    concat_kernel<<<(NN * FIN + 255) / 256, 256>>>(atom_emb, atom_pos, bufA);

    dim3 ggrid(HID / 128, NN / 128);   // (4, 64)

    // Layer 0: K = FIN = 128
    spmm_kernel<<<NN, FIN / 4>>>(bufA, bufB, FIN);
    gemm_tf32_softplus<FIN><<<ggrid, 256>>>(bufB, W0, b0, bufA);

    // Layer 1
    spmm_kernel<<<NN, HID / 4>>>(bufA, bufB, HID);
    gemm_tf32_softplus<HID><<<ggrid, 256>>>(bufB, W1, b1, bufA);

    // Layer 2
    spmm_kernel<<<NN, HID / 4>>>(bufA, bufB, HID);
    gemm_tf32_softplus<HID><<<ggrid, 256>>>(bufB, W2, b2, bufA);

    // Layer 3 -> write directly to d_out
    spmm_kernel<<<NN, HID / 4>>>(bufA, bufB, HID);
    gemm_tf32_softplus<HID><<<ggrid, 256>>>(bufB, W3, b3, out);
}

// round 4
// speedup vs baseline: 1.3715x; 1.3715x over previous
#include <cuda_runtime.h>
#include <math.h>
#include <stdint.h>

// Problem constants (fixed by reference)
#define NN   8192
#define EMB  125
#define POSD 3
#define FIN  128     // EMB + POSD
#define HID  512
#define SLOTS 256

// ---------------- device scratch (no allocation allowed) ----------------
__device__ int   g_col[NN * SLOTS];
__device__ int   g_deg[NN];
__device__ float g_norm[NN];
__device__ float g_bufA[NN * HID];
__device__ float g_bufB[NN * HID];

// ---------------- 1) build sparse structure + norms ----------------
__global__ void build_kernel(const float* __restrict__ adj) {
    int warp = threadIdx.x >> 5;
    int lane = threadIdx.x & 31;
    int row  = blockIdx.x * (blockDim.x >> 5) + warp;
    if (row >= NN) return;

    const float* arow = adj + (size_t)row * NN;
    int cnt = 0;
    for (int c0 = 0; c0 < NN; c0 += 32) {
        int c = c0 + lane;
        float v = arow[c];
        bool pred = (v != 0.0f) && (c != row);
        unsigned mask = __ballot_sync(0xFFFFFFFFu, pred);
        int pos = cnt + __popc(mask & ((1u << lane) - 1u));
        if (pred && pos < SLOTS) g_col[row * SLOTS + pos] = c;
        cnt += __popc(mask);
    }
    if (lane == 0) {
        g_deg[row]  = (cnt < SLOTS) ? cnt : SLOTS;
        g_norm[row] = rsqrtf(fmaxf((float)cnt, 1.0f));
    }
}

// ---------------- 2) concat emb||pos -> feat [NN, FIN] ----------------
__global__ void concat_kernel(const float* __restrict__ emb,
                              const float* __restrict__ pos,
                              float* __restrict__ out) {
    int idx = blockIdx.x * blockDim.x + threadIdx.x;
    if (idx >= NN * FIN) return;
    int i = idx / FIN, c = idx % FIN;
    out[idx] = (c < EMB) ? emb[i * EMB + c] : pos[i * POSD + (c - EMB)];
}

// ---------------- 3) SpMM (float4 per thread, one block per dst row) ----------------
__global__ void spmm_kernel(const float* __restrict__ feat,
                            float* __restrict__ agg, int C) {
    int i = blockIdx.x;
    int d = g_deg[i];
    __shared__ int   sc[SLOTS];
    __shared__ float sw[SLOTS];
    for (int k = threadIdx.x; k < d; k += blockDim.x) {
        int j = g_col[i * SLOTS + k];
        sc[k] = j;
        sw[k] = g_norm[j];
    }
    __syncthreads();
    int c4 = threadIdx.x * 4;
    float4 acc = make_float4(0.f, 0.f, 0.f, 0.f);
    for (int k = 0; k < d; k++) {
        float w = sw[k];
        float4 v = *(const float4*)&feat[(size_t)sc[k] * C + c4];
        acc.x = fmaf(w, v.x, acc.x);
        acc.y = fmaf(w, v.y, acc.y);
        acc.z = fmaf(w, v.z, acc.z);
        acc.w = fmaf(w, v.w, acc.w);
    }
    float ni = g_norm[i];
    acc.x *= ni; acc.y *= ni; acc.z *= ni; acc.w *= ni;
    *(float4*)&agg[(size_t)i * C + c4] = acc;
}

// ---------------- 4) TF32 tensor GEMM + bias + softplus ----------------
// A smem row-major [m][k] with LDA=20 pad -> STS.128 stores, ldmatrix.x4 frag loads.
// B smem [k][n] -> STS.128 stores, conflict-free scalar frag loads.
__device__ __forceinline__ uint32_t f2tf32(float f) {
    uint32_t r;
    asm("cvt.rna.tf32.f32 %0, %1;" : "=r"(r) : "f"(f));
    return r;
}

__device__ __forceinline__ void mma_tf32(float* d, const uint32_t* a, const uint32_t* b) {
    asm volatile(
        "mma.sync.aligned.m16n8k8.row.col.f32.tf32.tf32.f32 "
        "{%0,%1,%2,%3}, {%4,%5,%6,%7}, {%8,%9}, {%0,%1,%2,%3};\n"
        : "+f"(d[0]), "+f"(d[1]), "+f"(d[2]), "+f"(d[3])
        : "r"(a[0]), "r"(a[1]), "r"(a[2]), "r"(a[3]), "r"(b[0]), "r"(b[1]));
}

__device__ __forceinline__ void ldmat_x4(uint32_t* r, uint32_t saddr) {
    asm volatile(
        "ldmatrix.sync.aligned.m8n8.x4.shared.b16 {%0,%1,%2,%3}, [%4];\n"
        : "=r"(r[0]), "=r"(r[1]), "=r"(r[2]), "=r"(r[3])
        : "r"(saddr));
}

template <int K>
__global__ __launch_bounds__(256, 2) void gemm_tf32_softplus(
    const float* __restrict__ A,
    const float* __restrict__ Bw,
    const float* __restrict__ bias,
    float* __restrict__ Cout)
{
    constexpr int BM = 128, BN = 128, BK = 16;
    constexpr int LDA = BK + 4;   // 20 words: ldmatrix rows conflict-free
    constexpr int LDB = BN + 8;   // 136

    __shared__ __align__(16) uint32_t As[2][BM][LDA];  // 20.0 KB
    __shared__ __align__(16) uint32_t Bs[2][BK][LDB];  // 17.4 KB

    int tid  = threadIdx.x;
    int lane = tid & 31;
    int warp = tid >> 5;
    int g    = lane >> 2;     // 0..7
    int tg   = lane & 3;      // 0..3
    int wm   = (warp & 1) * 64;
    int wn   = (warp >> 1) * 32;
    int m0   = blockIdx.y * BM;
    int n0   = blockIdx.x * BN;

    // per-lane ldmatrix source coords within the A warp tile
    int lm_m = (lane & 7) + ((lane >> 3) & 1) * 8;  // row within 16-row frag
    int lm_k = (lane >> 4) * 4;                     // 0 or 4 within 8-wide kk

    float acc[4][4][4];
#pragma unroll
    for (int i = 0; i < 4; i++)
#pragma unroll
        for (int j = 0; j < 4; j++)
#pragma unroll
            for (int r = 0; r < 4; r++) acc[i][j][r] = 0.0f;

    float4 pa[2], pb[2];

    auto loadg = [&](int k0) {
#pragma unroll
        for (int i = 0; i < 2; i++) {
            int f  = tid * 2 + i;
            int ra = f >> 2,  ca = (f & 3) * 4;
            pa[i] = *(const float4*)&A[(size_t)(m0 + ra) * K + k0 + ca];
            int rb = f >> 5,  cb = (f & 31) * 4;
            pb[i] = *(const float4*)&Bw[(size_t)(k0 + rb) * HID + n0 + cb];
        }
    };
    auto stores = [&](int buf) {
#pragma unroll
        for (int i = 0; i < 2; i++) {
            int f  = tid * 2 + i;
            int ra = f >> 2,  ca = (f & 3) * 4;
            uint4 av;
            av.x = f2tf32(pa[i].x); av.y = f2tf32(pa[i].y);
            av.z = f2tf32(pa[i].z); av.w = f2tf32(pa[i].w);
            *(uint4*)&As[buf][ra][ca] = av;
            int rb = f >> 5,  cb = (f & 31) * 4;
            uint4 bv;
            bv.x = f2tf32(pb[i].x); bv.y = f2tf32(pb[i].y);
            bv.z = f2tf32(pb[i].z); bv.w = f2tf32(pb[i].w);
            *(uint4*)&Bs[buf][rb][cb] = bv;
        }
    };
    auto compute = [&](int buf) {
#pragma unroll
        for (int kk2 = 0; kk2 < 2; kk2++) {
            int kk8 = kk2 * 8;
            uint32_t a[4][4], b[4][2];
#pragma unroll
            for (int i = 0; i < 4; i++) {
                uint32_t saddr = (uint32_t)__cvta_generic_to_shared(
                    &As[buf][wm + i * 16 + lm_m][kk8 + lm_k]);
                ldmat_x4(a[i], saddr);
            }
#pragma unroll
            for (int j = 0; j < 4; j++) {
                int n = wn + j * 8 + g;
                b[j][0] = Bs[buf][kk8 + tg][n];
                b[j][1] = Bs[buf][kk8 + tg + 4][n];
            }
#pragma unroll
            for (int i = 0; i < 4; i++)
#pragma unroll
                for (int j = 0; j < 4; j++)
                    mma_tf32(acc[i][j], a[i], b[j]);
        }
    };

    constexpr int NK = K / BK;
    loadg(0);
    stores(0);
    __syncthreads();
#pragma unroll 1
    for (int t = 0; t < NK; t++) {
        if (t + 1 < NK) loadg((t + 1) * BK);
        compute(t & 1);
        if (t + 1 < NK) {
            stores((t + 1) & 1);
            __syncthreads();
        }
    }

    // epilogue: bias + fast stable softplus
#pragma unroll
    for (int i = 0; i < 4; i++) {
        int row = m0 + wm + i * 16 + g;
#pragma unroll
        for (int j = 0; j < 4; j++) {
            int col = n0 + wn + j * 8 + tg * 2;
            float bx = bias[col], by = bias[col + 1];
            float x0 = acc[i][j][0] + bx;
            float x1 = acc[i][j][1] + by;
            float x2 = acc[i][j][2] + bx;
            float x3 = acc[i][j][3] + by;
            float2 o0, o1;
            o0.x = fmaxf(x0, 0.f) + __logf(1.0f + __expf(-fabsf(x0)));
            o0.y = fmaxf(x1, 0.f) + __logf(1.0f + __expf(-fabsf(x1)));
            o1.x = fmaxf(x2, 0.f) + __logf(1.0f + __expf(-fabsf(x2)));
            o1.y = fmaxf(x3, 0.f) + __logf(1.0f + __expf(-fabsf(x3)));
            *(float2*)&Cout[(size_t)row * HID + col]       = o0;
            *(float2*)&Cout[(size_t)(row + 8) * HID + col] = o1;
        }
    }
}

// ---------------- launch ----------------
extern "C" void kernel_launch(void* const* d_in, const int* in_sizes, int n_in,
                              void* d_out, int out_size) {
    const float* atom_pos = (const float*)d_in[0];
    const float* dist_adj = (const float*)d_in[1];
    const float* atom_emb = (const float*)d_in[2];
    const float* W0 = (const float*)d_in[3];
    const float* b0 = (const float*)d_in[4];
    const float* W1 = (const float*)d_in[5];
    const float* b1 = (const float*)d_in[6];
    const float* W2 = (const float*)d_in[7];
    const float* b2 = (const float*)d_in[8];
    const float* W3 = (const float*)d_in[9];
    const float* b3 = (const float*)d_in[10];
    float* out = (float*)d_out;

    float *bufA, *bufB;
    cudaGetSymbolAddress((void**)&bufA, g_bufA);
    cudaGetSymbolAddress((void**)&bufB, g_bufB);

    build_kernel<<<NN / 8, 256>>>(dist_adj);
    concat_kernel<<<(NN * FIN + 255) / 256, 256>>>(atom_emb, atom_pos, bufA);

    dim3 ggrid(HID / 128, NN / 128);   // (4, 64)

    // Layer 0: K = FIN = 128
    spmm_kernel<<<NN, FIN / 4>>>(bufA, bufB, FIN);
    gemm_tf32_softplus<FIN><<<ggrid, 256>>>(bufB, W0, b0, bufA);

    // Layer 1
    spmm_kernel<<<NN, HID / 4>>>(bufA, bufB, HID);
    gemm_tf32_softplus<HID><<<ggrid, 256>>>(bufB, W1, b1, bufA);

    // Layer 2
    spmm_kernel<<<NN, HID / 4>>>(bufA, bufB, HID);
    gemm_tf32_softplus<HID><<<ggrid, 256>>>(bufB, W2, b2, bufA);

    // Layer 3 -> write directly to d_out
    spmm_kernel<<<NN, HID / 4>>>(bufA, bufB, HID);
    gemm_tf32_softplus<HID><<<ggrid, 256>>>(bufB, W3, b3, out);
}